// round 15
// baseline (speedup 1.0000x reference)
#include <cuda_runtime.h>
#include <cuda_bf16.h>

#define NN 4096
#define DD 64
#define HH 4
#define BBOND 4
#define E2 36864      /* E + N : per-direction edge count (self-loops appended) */
#define ET 73728      /* 2 * E2 : total directed edges after symmetrization */
#define CAP 128       /* max row degree (Po(16)+2; 3x margin) */

typedef unsigned long long u64;

/* ---- warp-level bf16 MMA (sm_80+, works on base sm_100 target) --------- */
__device__ __forceinline__ void mma_bf16(float* c,
        unsigned a0, unsigned a1, unsigned a2, unsigned a3,
        unsigned b0, unsigned b1) {
    asm volatile(
        "mma.sync.aligned.m16n8k16.row.col.f32.bf16.bf16.f32 "
        "{%0,%1,%2,%3}, {%4,%5,%6,%7}, {%8,%9}, {%0,%1,%2,%3};"
        : "+f"(c[0]), "+f"(c[1]), "+f"(c[2]), "+f"(c[3])
        : "r"(a0), "r"(a1), "r"(a2), "r"(a3), "r"(b0), "r"(b1));
}

/* pack two fp32 into bf16x2 (lo element in low 16 bits) in one cvt */
__device__ __forceinline__ unsigned cvt2hi(float lo, float hi) {
    unsigned r;
    asm("cvt.rn.bf16x2.f32 %0, %1, %2;" : "=r"(r) : "f"(hi), "f"(lo));
    return r;
}
/* split pair into bf16 hi-pair + bf16 residual-pair */
__device__ __forceinline__ void split2(float lo, float hi, unsigned& hp, unsigned& lp) {
    hp = cvt2hi(lo, hi);
    float fl = __uint_as_float(hp << 16);
    float fh = __uint_as_float(hp & 0xffff0000u);
    lp = cvt2hi(lo - fl, hi - fh);
}

/* ------------------------------ scratch --------------------------------- */
__device__ float    g_V[NN * DD];
__device__ unsigned g_Qhi[NN * 32], g_Qlo[NN * 32];
__device__ unsigned g_Khi[NN * 32], g_Klo[NN * 32];
__device__ unsigned g_W0hi[BBOND * HH * 4096], g_W0lo[BBOND * HH * 4096];
__device__ unsigned g_W1hi[BBOND * HH * 2048], g_W1lo[BBOND * HH * 2048];
__device__ float g_scores[HH * ET];
__device__ float g_att[NN * HH * DD];
__device__ int   g_rowcnt[NN];
__device__ int   g_rowoff[NN + 1];
__device__ int   g_rowfill[NN];
__device__ int   g_bondcnt[BBOND];
__device__ int   g_bondoff[BBOND + 1];
__device__ int   g_bondfill[BBOND];
__device__ int   g_binned[ET];
__device__ int   g_colpack[ET];    /* (eid<<12)|col */

/* ------------------------------ zero counters --------------------------- */
__global__ void k_zero() {
    int i = blockIdx.x * blockDim.x + threadIdx.x;
    if (i < NN) g_rowcnt[i] = 0;
    if (i < BBOND) g_bondcnt[i] = 0;
}

/* ----------- one-time weight splitting into fragment layout ------------- */
__global__ void __launch_bounds__(128) k_wsplit(const float* __restrict__ W0,
                                                const float* __restrict__ W1) {
    int combo = blockIdx.x;
    int tid = threadIdx.x;
    /* W1: [n][kp] pairs */
    for (int idx = tid; idx < 2048; idx += 128) {
        int n = idx & 63, kp = idx >> 6;
        float w0 = W1[combo * 4096 + (kp * 2) * 64 + n];
        float w1 = W1[combo * 4096 + (kp * 2 + 1) * 64 + n];
        unsigned hp, lp;
        split2(w0, w1, hp, lp);
        g_W1hi[combo * 2048 + n * 32 + kp] = hp;
        g_W1lo[combo * 2048 + n * 32 + kp] = lp;
    }
    /* W0: [ph][n][kp] */
    for (int idx = tid; idx < 4096; idx += 128) {
        int n = idx & 63, kp = (idx >> 6) & 31, ph = idx >> 11;
        const float* Wb = W0 + combo * 8192 + ph * 4096;
        float w0 = Wb[(kp * 2) * 64 + n];
        float w1 = Wb[(kp * 2 + 1) * 64 + n];
        unsigned hp, lp;
        split2(w0, w1, hp, lp);
        g_W0hi[combo * 4096 + ph * 2048 + n * 32 + kp] = hp;
        g_W0lo[combo * 4096 + ph * 2048 + n * 32 + kp] = lp;
    }
}

/* ------ QKV projections (smem weights) + fused edge histogram ----------- */
#define QKV_SMEM (4096 * 3 * 4 + 2048 * 4 + 192 * 4)
__global__ void __launch_bounds__(256) k_qkv(
        const float* __restrict__ emb,
        const float* __restrict__ Qw, const float* __restrict__ Qb,
        const float* __restrict__ Kw, const float* __restrict__ Kb,
        const float* __restrict__ Vw, const float* __restrict__ Vb,
        const int* __restrict__ src, const int* __restrict__ dst,
        const int* __restrict__ bond) {
    extern __shared__ float qs[];
    __shared__ int sbh[BBOND];
    float* sWq = qs;
    float* sWk = qs + 4096;
    float* sWv = qs + 8192;
    float* seb = qs + 12288;          /* 32 x 64 */
    float* sbq = qs + 14336;
    float* sbk = qs + 14400;
    float* sbv = qs + 14464;
    int tid = threadIdx.x;
    int n0 = blockIdx.x * 32;
    if (tid < BBOND) sbh[tid] = 0;
    for (int i = tid; i < 1024; i += 256) {
        reinterpret_cast<float4*>(sWq)[i] = reinterpret_cast<const float4*>(Qw)[i];
        reinterpret_cast<float4*>(sWk)[i] = reinterpret_cast<const float4*>(Kw)[i];
        reinterpret_cast<float4*>(sWv)[i] = reinterpret_cast<const float4*>(Vw)[i];
    }
    for (int i = tid; i < 512; i += 256)
        reinterpret_cast<float4*>(seb)[i] =
            reinterpret_cast<const float4*>(emb + (size_t)n0 * 64)[i];
    if (tid < 64) { sbq[tid] = Qb[tid]; sbk[tid] = Kb[tid]; sbv[tid] = Vb[tid]; }
    __syncthreads();
    int k = tid & 63, rg = tid >> 6;   /* 4 groups x 8 rows */
    float aq[8], ak[8], av[8];
#pragma unroll
    for (int j = 0; j < 8; j++) { aq[j] = sbq[k]; ak[j] = sbk[k]; av[j] = sbv[k]; }
#pragma unroll 4
    for (int f = 0; f < 64; f++) {
        float wq = sWq[f * 64 + k], wk = sWk[f * 64 + k], wv = sWv[f * 64 + k];
#pragma unroll
        for (int j = 0; j < 8; j++) {
            float e = seb[(rg * 8 + j) * 64 + f];
            aq[j] = fmaf(e, wq, aq[j]);
            ak[j] = fmaf(e, wk, ak[j]);
            av[j] = fmaf(e, wv, av[j]);
        }
    }
#pragma unroll
    for (int j = 0; j < 8; j++) {
        int row = n0 + rg * 8 + j;
        g_V[row * 64 + k] = av[j];
        float pq = __shfl_xor_sync(0xffffffffu, aq[j], 1);
        float pk = __shfl_xor_sync(0xffffffffu, ak[j], 1);
        if (!(k & 1)) {
            unsigned hp, lp;
            split2(aq[j], pq, hp, lp);
            g_Qhi[row * 32 + (k >> 1)] = hp;
            g_Qlo[row * 32 + (k >> 1)] = lp;
            split2(ak[j], pk, hp, lp);
            g_Khi[row * 32 + (k >> 1)] = hp;
            g_Klo[row * 32 + (k >> 1)] = lp;
        }
    }
    /* fused edge histogram (independent work) */
    for (int e = blockIdx.x * 256 + tid; e < ET; e += 128 * 256) {
        int eb = (e < E2) ? e : e - E2;
        atomicAdd(&sbh[bond[eb]], 1);
        int row = (e < E2) ? src[e] : dst[e - E2];
        atomicAdd(&g_rowcnt[row], 1);
    }
    __syncthreads();
    if (tid < BBOND) atomicAdd(&g_bondcnt[tid], sbh[tid]);
}

/* ----------------------- exclusive scan (single block) ------------------ */
__global__ void k_scan() {
    __shared__ int wsum[32];
    int tid = threadIdx.x;
    int lane = tid & 31, w = tid >> 5;
    int v[4];
#pragma unroll
    for (int i = 0; i < 4; i++) v[i] = g_rowcnt[tid * 4 + i];
    int ssum = v[0] + v[1] + v[2] + v[3];
    int x = ssum;
#pragma unroll
    for (int o = 1; o < 32; o <<= 1) {
        int y = __shfl_up_sync(0xffffffffu, x, o);
        if (lane >= o) x += y;
    }
    if (lane == 31) wsum[w] = x;
    __syncthreads();
    if (w == 0) {
        int y = wsum[lane];
#pragma unroll
        for (int o = 1; o < 32; o <<= 1) {
            int z = __shfl_up_sync(0xffffffffu, y, o);
            if (lane >= o) y += z;
        }
        wsum[lane] = y;
    }
    __syncthreads();
    int base = x - ssum + (w > 0 ? wsum[w - 1] : 0);
    int run = base;
#pragma unroll
    for (int i = 0; i < 4; i++) {
        g_rowoff[tid * 4 + i]  = run;
        g_rowfill[tid * 4 + i] = run;
        run += v[i];
    }
    if (tid == 1023) g_rowoff[NN] = run;
    if (tid == 0) {
        int accb = 0;
        for (int b = 0; b < BBOND; b++) {
            g_bondoff[b] = accb; g_bondfill[b] = accb; accb += g_bondcnt[b];
        }
        g_bondoff[BBOND] = accb;
    }
}

/* --------------- scatter into bins / CSR (block-aggregated) ------------- */
__global__ void k_scat(const int* __restrict__ src, const int* __restrict__ dst,
                       const int* __restrict__ bond) {
    __shared__ int sb[BBOND];
    __shared__ int sbase[BBOND];
    int tid = threadIdx.x;
    if (tid < BBOND) sb[tid] = 0;
    __syncthreads();
    int e = blockIdx.x * blockDim.x + tid;
    int b = 0, loc = 0;
    if (e < ET) {
        int eb = (e < E2) ? e : e - E2;
        b = bond[eb];
        loc = atomicAdd(&sb[b], 1);
    }
    __syncthreads();
    if (tid < BBOND) sbase[tid] = atomicAdd(&g_bondfill[tid], sb[tid]);
    __syncthreads();
    if (e < ET) {
        g_binned[sbase[b] + loc] = e;
        int row, col;
        if (e < E2) { row = src[e]; col = dst[e]; }
        else        { row = dst[e - E2]; col = src[e - E2]; }
        int p2 = atomicAdd(&g_rowfill[row], 1);
        g_colpack[p2] = (e << 12) | col;
    }
}

/* ------ FUSED edge kernel: layer0 (Q,K parts) + relu + layer1 + score ---- */
/* 8 warps as 4 m-groups x 2 n-groups, mt=2 x nt=4, 3-term bf16-split MMA.  */
#define ASTRIDE 36
struct ESmem {
    unsigned Ahi[128 * ASTRIDE];
    unsigned Alo[128 * ASTRIDE];
    unsigned Bhi[64 * ASTRIDE];
    unsigned Blo[64 * ASTRIDE];
    float red[2][128];
    float b0v[64], b1v[64], W2v[64];
    int eid[128], sn[128], dn[128];
};
#define EDGE_SMEM ((int)sizeof(ESmem))

__device__ __forceinline__ void mma_pass(const unsigned* __restrict__ Ahi,
                                         const unsigned* __restrict__ Alo,
                                         const unsigned* __restrict__ Bhi,
                                         const unsigned* __restrict__ Blo,
                                         int rb, int cb, int qg, int m4,
                                         float acc[2][4][4]) {
#pragma unroll
    for (int kt = 0; kt < 4; kt++) {
        int kp0 = kt * 8 + m4;
        unsigned ah[2][4], al[2][4];
#pragma unroll
        for (int mt = 0; mt < 2; mt++) {
            int r = rb + mt * 16 + qg;
            ah[mt][0] = Ahi[r * ASTRIDE + kp0];
            ah[mt][1] = Ahi[(r + 8) * ASTRIDE + kp0];
            ah[mt][2] = Ahi[r * ASTRIDE + kp0 + 4];
            ah[mt][3] = Ahi[(r + 8) * ASTRIDE + kp0 + 4];
            al[mt][0] = Alo[r * ASTRIDE + kp0];
            al[mt][1] = Alo[(r + 8) * ASTRIDE + kp0];
            al[mt][2] = Alo[r * ASTRIDE + kp0 + 4];
            al[mt][3] = Alo[(r + 8) * ASTRIDE + kp0 + 4];
        }
#pragma unroll
        for (int nt = 0; nt < 4; nt++) {
            int n = cb + nt * 8 + qg;
            unsigned bh0 = Bhi[n * ASTRIDE + kp0];
            unsigned bh1 = Bhi[n * ASTRIDE + kp0 + 4];
            unsigned bl0 = Blo[n * ASTRIDE + kp0];
            unsigned bl1 = Blo[n * ASTRIDE + kp0 + 4];
#pragma unroll
            for (int mt = 0; mt < 2; mt++) {
                mma_bf16(acc[mt][nt], ah[mt][0], ah[mt][1], ah[mt][2], ah[mt][3], bh0, bh1);
                mma_bf16(acc[mt][nt], ah[mt][0], ah[mt][1], ah[mt][2], ah[mt][3], bl0, bl1);
                mma_bf16(acc[mt][nt], al[mt][0], al[mt][1], al[mt][2], al[mt][3], bh0, bh1);
            }
        }
    }
}

__global__ void __launch_bounds__(256, 3)
k_edges(const int* __restrict__ src, const int* __restrict__ dst,
        const float* __restrict__ b0,
        const float* __restrict__ b1, const float* __restrict__ W2,
        const float* __restrict__ b2) {
    extern __shared__ char smraw[];
    ESmem& s = *reinterpret_cast<ESmem*>(smraw);
    int tid = threadIdx.x;
    int lane = tid & 31, wid = tid >> 5;

    /* tile mapping */
    int t = blockIdx.x;
    int bt = -1, base = 0, nE = 0;
#pragma unroll
    for (int b = 0; b < BBOND; b++) {
        int lo = g_bondoff[b], hi = g_bondoff[b + 1];
        int nt = ((hi - lo) + 127) >> 7;
        if (bt < 0) {
            if (t < nt) { bt = b; base = lo + t * 128; nE = min(128, hi - base); }
            else t -= nt;
        }
    }
    if (bt < 0) return;
    int h = blockIdx.y;
    int combo = bt * 4 + h;

    if (tid < 64) {
        s.b0v[tid] = b0[combo * 64 + tid];
        s.b1v[tid] = b1[combo * 64 + tid];
        s.W2v[tid] = W2[combo * 64 + tid];
    }
    if (tid < nE) {
        int e = g_binned[base + tid];
        s.eid[tid] = e;
        if (e < E2) { s.sn[tid] = src[e];      s.dn[tid] = dst[e]; }
        else        { s.sn[tid] = dst[e - E2]; s.dn[tid] = src[e - E2]; }
    }
    __syncthreads();

    int qg = lane >> 2, m4 = lane & 3;
    int mg = wid >> 1, ng = wid & 1;
    int rb = mg * 32, cb = ng * 32;
    int gr = tid >> 1, ghf = tid & 1;   /* gather: 2 threads per edge row */

    float acc[2][4][4];
#pragma unroll
    for (int mt = 0; mt < 2; mt++)
#pragma unroll
        for (int nt = 0; nt < 4; nt++)
#pragma unroll
            for (int c = 0; c < 4; c++) acc[mt][nt][c] = 0.f;

    /* ---- layer-0 pass 1: A <- Q[sn], B <- W0 top half ---- */
    {
        const uint4* Qh4 = reinterpret_cast<const uint4*>(g_Qhi);
        const uint4* Ql4 = reinterpret_cast<const uint4*>(g_Qlo);
        if (gr < nE) {
            int n = s.sn[gr];
#pragma unroll
            for (int j = 0; j < 4; j++) {
                int c4 = ghf * 4 + j;
                *reinterpret_cast<uint4*>(&s.Ahi[gr * ASTRIDE + c4 * 4]) = Qh4[n * 8 + c4];
                *reinterpret_cast<uint4*>(&s.Alo[gr * ASTRIDE + c4 * 4]) = Ql4[n * 8 + c4];
            }
        } else {
            uint4 z = make_uint4(0, 0, 0, 0);
#pragma unroll
            for (int j = 0; j < 4; j++) {
                int c4 = ghf * 4 + j;
                *reinterpret_cast<uint4*>(&s.Ahi[gr * ASTRIDE + c4 * 4]) = z;
                *reinterpret_cast<uint4*>(&s.Alo[gr * ASTRIDE + c4 * 4]) = z;
            }
        }
        const uint4* Bh4 = reinterpret_cast<const uint4*>(g_W0hi) + (size_t)combo * 1024;
        const uint4* Bl4 = reinterpret_cast<const uint4*>(g_W0lo) + (size_t)combo * 1024;
        for (int idx = tid; idx < 512; idx += 256) {
            int n = idx >> 3, c4 = idx & 7;
            *reinterpret_cast<uint4*>(&s.Bhi[n * ASTRIDE + c4 * 4]) = Bh4[idx];
            *reinterpret_cast<uint4*>(&s.Blo[n * ASTRIDE + c4 * 4]) = Bl4[idx];
        }
    }
    __syncthreads();
    mma_pass(s.Ahi, s.Alo, s.Bhi, s.Blo, rb, cb, qg, m4, acc);
    __syncthreads();

    /* ---- layer-0 pass 2: A <- K[dn], B <- W0 bottom half ---- */
    {
        const uint4* Kh4 = reinterpret_cast<const uint4*>(g_Khi);
        const uint4* Kl4 = reinterpret_cast<const uint4*>(g_Klo);
        if (gr < nE) {
            int n = s.dn[gr];
#pragma unroll
            for (int j = 0; j < 4; j++) {
                int c4 = ghf * 4 + j;
                *reinterpret_cast<uint4*>(&s.Ahi[gr * ASTRIDE + c4 * 4]) = Kh4[n * 8 + c4];
                *reinterpret_cast<uint4*>(&s.Alo[gr * ASTRIDE + c4 * 4]) = Kl4[n * 8 + c4];
            }
        } else {
            uint4 z = make_uint4(0, 0, 0, 0);
#pragma unroll
            for (int j = 0; j < 4; j++) {
                int c4 = ghf * 4 + j;
                *reinterpret_cast<uint4*>(&s.Ahi[gr * ASTRIDE + c4 * 4]) = z;
                *reinterpret_cast<uint4*>(&s.Alo[gr * ASTRIDE + c4 * 4]) = z;
            }
        }
        const uint4* Bh4 = reinterpret_cast<const uint4*>(g_W0hi) + (size_t)combo * 1024 + 512;
        const uint4* Bl4 = reinterpret_cast<const uint4*>(g_W0lo) + (size_t)combo * 1024 + 512;
        for (int idx = tid; idx < 512; idx += 256) {
            int n = idx >> 3, c4 = idx & 7;
            *reinterpret_cast<uint4*>(&s.Bhi[n * ASTRIDE + c4 * 4]) = Bh4[idx];
            *reinterpret_cast<uint4*>(&s.Blo[n * ASTRIDE + c4 * 4]) = Bl4[idx];
        }
    }
    __syncthreads();
    mma_pass(s.Ahi, s.Alo, s.Bhi, s.Blo, rb, cb, qg, m4, acc);
    __syncthreads();   /* all reads of A done before h0 overwrite */

    /* ---- h0 = relu(acc + b0) -> split back into A; B <- W1 ---- */
#pragma unroll
    for (int mt = 0; mt < 2; mt++) {
        int r1 = rb + mt * 16 + qg, r2 = r1 + 8;
#pragma unroll
        for (int nt = 0; nt < 4; nt++) {
            int col = cb + nt * 8 + m4 * 2;
            int kpi = (col >> 1);
            float bb0 = s.b0v[col], bb1 = s.b0v[col + 1];
            unsigned hp, lp;
            split2(fmaxf(acc[mt][nt][0] + bb0, 0.f),
                   fmaxf(acc[mt][nt][1] + bb1, 0.f), hp, lp);
            s.Ahi[r1 * ASTRIDE + kpi] = hp;
            s.Alo[r1 * ASTRIDE + kpi] = lp;
            split2(fmaxf(acc[mt][nt][2] + bb0, 0.f),
                   fmaxf(acc[mt][nt][3] + bb1, 0.f), hp, lp);
            s.Ahi[r2 * ASTRIDE + kpi] = hp;
            s.Alo[r2 * ASTRIDE + kpi] = lp;
            /* reset accumulators for layer 1 */
            acc[mt][nt][0] = 0.f; acc[mt][nt][1] = 0.f;
            acc[mt][nt][2] = 0.f; acc[mt][nt][3] = 0.f;
        }
    }
    {
        const uint4* Bh4 = reinterpret_cast<const uint4*>(g_W1hi) + (size_t)combo * 512;
        const uint4* Bl4 = reinterpret_cast<const uint4*>(g_W1lo) + (size_t)combo * 512;
        for (int idx = tid; idx < 512; idx += 256) {
            int n = idx >> 3, c4 = idx & 7;
            *reinterpret_cast<uint4*>(&s.Bhi[n * ASTRIDE + c4 * 4]) = Bh4[idx];
            *reinterpret_cast<uint4*>(&s.Blo[n * ASTRIDE + c4 * 4]) = Bl4[idx];
        }
    }
    __syncthreads();

    /* ---- layer 1 ---- */
    mma_pass(s.Ahi, s.Alo, s.Bhi, s.Blo, rb, cb, qg, m4, acc);

    /* epilogue: relu + W2 partial dot over this warp's 32 cols */
    float p[4] = {0.f, 0.f, 0.f, 0.f};
#pragma unroll
    for (int nt = 0; nt < 4; nt++) {
#pragma unroll
        for (int j = 0; j < 2; j++) {
            int col = cb + nt * 8 + m4 * 2 + j;
            float bb = s.b1v[col], ww = s.W2v[col];
            p[0] = fmaf(fmaxf(acc[0][nt][j] + bb, 0.f), ww, p[0]);
            p[1] = fmaf(fmaxf(acc[0][nt][2 + j] + bb, 0.f), ww, p[1]);
            p[2] = fmaf(fmaxf(acc[1][nt][j] + bb, 0.f), ww, p[2]);
            p[3] = fmaf(fmaxf(acc[1][nt][2 + j] + bb, 0.f), ww, p[3]);
        }
    }
#pragma unroll
    for (int i = 0; i < 4; i++) {
        p[i] += __shfl_xor_sync(0xffffffffu, p[i], 1);
        p[i] += __shfl_xor_sync(0xffffffffu, p[i], 2);
    }
    if (m4 == 0) {
        s.red[ng][rb + qg]      = p[0];
        s.red[ng][rb + qg + 8]  = p[1];
        s.red[ng][rb + qg + 16] = p[2];
        s.red[ng][rb + qg + 24] = p[3];
    }
    __syncthreads();
    if (tid < 128 && tid < nE) {
        float sc = s.red[0][tid] + s.red[1][tid] + b2[combo];
        sc = (sc >= 0.f) ? sc : 0.2f * sc;
        g_scores[h * ET + s.eid[tid]] = sc;
    }
}

/* -------------- per-row sparse softmax (dedup, last-write-wins) --------- */
struct SoftSmem {
    float VS[CAP * 64];
    float scs[4][CAP];
    int   pk[CAP];
    int   srt[CAP];
    unsigned char kept[CAP];
};

__global__ void __launch_bounds__(128) k_soft() {
    extern __shared__ char smem_raw[];
    SoftSmem& s = *reinterpret_cast<SoftSmem*>(smem_raw);
    int row = blockIdx.x;
    int tid = threadIdx.x;
    int off0 = g_rowoff[row];
    int deg = g_rowoff[row + 1] - off0;
    if (deg > CAP) deg = CAP;
    for (int a = tid; a < deg; a += 128) s.pk[a] = g_colpack[off0 + a];
    __syncthreads();
    for (int a = tid; a < deg; a += 128) {
        int p = s.pk[a];
        int rk = 0;
        for (int b = 0; b < deg; b++) rk += (s.pk[b] < p);
        s.srt[rk] = p;
    }
    __syncthreads();
    for (int a = tid; a < deg; a += 128) {
        int col = s.srt[a] & 0xFFF;
        unsigned char kf = 1;
        for (int b = a + 1; b < deg; b++)
            if ((s.srt[b] & 0xFFF) == col) { kf = 0; break; }
        s.kept[a] = kf;
    }
    __syncthreads();
    for (int h2 = 0; h2 < 4; h2++)
        for (int a = tid; a < deg; a += 128)
            s.scs[h2][a] = g_scores[h2 * ET + (s.srt[a] >> 12)];
    for (int idx = tid; idx < deg * 16; idx += 128) {
        int a = idx >> 4, cv = idx & 15;
        int col = s.srt[a] & 0xFFF;
        reinterpret_cast<float4*>(s.VS + a * 64)[cv] =
            reinterpret_cast<const float4*>(g_V + col * 64)[cv];
    }
    __syncthreads();

    int lane = tid & 31, h = tid >> 5;
    float m = -1e30f;
    for (int a = lane; a < deg; a += 32)
        if (s.kept[a]) m = fmaxf(m, s.scs[h][a]);
#pragma unroll
    for (int o = 16; o > 0; o >>= 1) m = fmaxf(m, __shfl_xor_sync(0xffffffffu, m, o));
    float dsum = 0.f;
    for (int a = lane; a < deg; a += 32) {
        float p = s.kept[a] ? __expf(s.scs[h][a] - m) : 0.f;
        s.scs[h][a] = p;
        dsum += p;
    }
#pragma unroll
    for (int o = 16; o > 0; o >>= 1) dsum += __shfl_xor_sync(0xffffffffu, dsum, o);
    __syncwarp();
    float inv = 1.f / dsum;
    float acc0 = 0.f, acc1 = 0.f, acc2 = 0.f, acc3 = 0.f;
    int a = 0;
    for (; a + 1 < deg; a += 2) {
        float w0 = s.scs[h][a] * inv;
        float w1 = s.scs[h][a + 1] * inv;
        acc0 = fmaf(w0, s.VS[a * 64 + lane], acc0);
        acc1 = fmaf(w0, s.VS[a * 64 + 32 + lane], acc1);
        acc2 = fmaf(w1, s.VS[(a + 1) * 64 + lane], acc2);
        acc3 = fmaf(w1, s.VS[(a + 1) * 64 + 32 + lane], acc3);
    }
    if (a < deg) {
        float w0 = s.scs[h][a] * inv;
        acc0 = fmaf(w0, s.VS[a * 64 + lane], acc0);
        acc1 = fmaf(w0, s.VS[a * 64 + 32 + lane], acc1);
    }
    g_att[row * 256 + h * 64 + lane]      = acc0 + acc2;
    g_att[row * 256 + h * 64 + 32 + lane] = acc1 + acc3;
}

/* ------------------------------ final projection ------------------------ */
__global__ void __launch_bounds__(256) k_proj(const float* __restrict__ Pw,
                                              const float* __restrict__ Pb,
                                              float* __restrict__ out) {
    __shared__ float ats[16 * 256];
    int tid = threadIdx.x;
    int r0 = blockIdx.x * 16;
    for (int idx = tid; idx < 1024; idx += 256)
        reinterpret_cast<float4*>(ats)[idx] =
            reinterpret_cast<const float4*>(g_att + (size_t)r0 * 256)[idx];
    __syncthreads();
    int c = tid & 63, rg = tid >> 6;
    float acc[4];
    float pb = Pb[c];
#pragma unroll
    for (int r = 0; r < 4; r++) acc[r] = pb;
#pragma unroll 4
    for (int k = 0; k < 256; k++) {
        float w = Pw[k * 64 + c];
#pragma unroll
        for (int r = 0; r < 4; r++)
            acc[r] = fmaf(ats[(rg * 4 + r) * 256 + k], w, acc[r]);
    }
#pragma unroll
    for (int r = 0; r < 4; r++)
        out[(r0 + rg * 4 + r) * 64 + c] = acc[r];
}

/* ------------------------------ launcher -------------------------------- */
extern "C" void kernel_launch(void* const* d_in, const int* in_sizes, int n_in,
                              void* d_out, int out_size) {
    const float* emb = (const float*)d_in[0];
    const float* Qw  = (const float*)d_in[1];
    const float* Qb  = (const float*)d_in[2];
    const float* Kw  = (const float*)d_in[3];
    const float* Kb  = (const float*)d_in[4];
    const float* Vw  = (const float*)d_in[5];
    const float* Vb  = (const float*)d_in[6];
    const float* W0  = (const float*)d_in[7];
    const float* b0  = (const float*)d_in[8];
    const float* W1  = (const float*)d_in[9];
    const float* b1  = (const float*)d_in[10];
    const float* W2  = (const float*)d_in[11];
    const float* b2  = (const float*)d_in[12];
    const float* Pw  = (const float*)d_in[13];
    const float* Pb  = (const float*)d_in[14];
    const int*   src = (const int*)d_in[15];
    const int*   dst = (const int*)d_in[16];
    const int*   bnd = (const int*)d_in[17];
    float* out = (float*)d_out;

    cudaFuncSetAttribute(k_qkv, cudaFuncAttributeMaxDynamicSharedMemorySize, QKV_SMEM);
    cudaFuncSetAttribute(k_edges, cudaFuncAttributeMaxDynamicSharedMemorySize, EDGE_SMEM);
    cudaFuncSetAttribute(k_soft, cudaFuncAttributeMaxDynamicSharedMemorySize,
                         (int)sizeof(SoftSmem));

    k_zero<<<16, 256>>>();
    k_wsplit<<<16, 128>>>(W0, W1);
    k_qkv<<<NN / 32, 256, QKV_SMEM>>>(emb, Qw, Qb, Kw, Kb, Vw, Vb, src, dst, bnd);
    k_scan<<<1, 1024>>>();
    k_scat<<<ET / 256, 256>>>(src, dst, bnd);
    k_edges<<<dim3(579, 4), 256, EDGE_SMEM>>>(src, dst, b0, b1, W2, b2);
    k_soft<<<NN, 128, sizeof(SoftSmem)>>>();
    k_proj<<<NN / 16, 256>>>(Pw, Pb, out);
}

// round 16
// speedup vs baseline: 1.2636x; 1.2636x over previous
#include <cuda_runtime.h>
#include <cuda_bf16.h>

#define NN 4096
#define DD 64
#define HH 4
#define BBOND 4
#define E2 36864      /* E + N : per-direction edge count (self-loops appended) */
#define ET 73728      /* 2 * E2 : total directed edges after symmetrization */
#define CAP 128       /* max row degree (Po(16)+2; 3x margin) */
#define BINCAP 32768  /* max edges per bond bin (expected ~18-25k) */

typedef unsigned long long u64;

/* ---- warp-level bf16 MMA (sm_80+, works on base sm_100 target) --------- */
__device__ __forceinline__ void mma_bf16(float* c,
        unsigned a0, unsigned a1, unsigned a2, unsigned a3,
        unsigned b0, unsigned b1) {
    asm volatile(
        "mma.sync.aligned.m16n8k16.row.col.f32.bf16.bf16.f32 "
        "{%0,%1,%2,%3}, {%4,%5,%6,%7}, {%8,%9}, {%0,%1,%2,%3};"
        : "+f"(c[0]), "+f"(c[1]), "+f"(c[2]), "+f"(c[3])
        : "r"(a0), "r"(a1), "r"(a2), "r"(a3), "r"(b0), "r"(b1));
}

/* pack two fp32 into bf16x2 (lo element in low 16 bits) in one cvt */
__device__ __forceinline__ unsigned cvt2hi(float lo, float hi) {
    unsigned r;
    asm("cvt.rn.bf16x2.f32 %0, %1, %2;" : "=r"(r) : "f"(hi), "f"(lo));
    return r;
}
/* split pair into bf16 hi-pair + bf16 residual-pair */
__device__ __forceinline__ void split2(float lo, float hi, unsigned& hp, unsigned& lp) {
    hp = cvt2hi(lo, hi);
    float fl = __uint_as_float(hp << 16);
    float fh = __uint_as_float(hp & 0xffff0000u);
    lp = cvt2hi(lo - fl, hi - fh);
}

/* ------------------------------ scratch --------------------------------- */
__device__ float    g_V[NN * DD];
__device__ unsigned g_Qhi[NN * 32], g_Qlo[NN * 32];
__device__ unsigned g_Khi[NN * 32], g_Klo[NN * 32];
__device__ unsigned g_W0hi[BBOND * HH * 4096], g_W0lo[BBOND * HH * 4096];
__device__ unsigned g_W1hi[BBOND * HH * 2048], g_W1lo[BBOND * HH * 2048];
__device__ float g_QW0[BBOND * HH * NN * DD];
__device__ float g_KW0[BBOND * HH * NN * DD];
__device__ float g_scores[HH * ET];
__device__ float g_att[NN * HH * DD];
__device__ int   g_rowfill[NN];
__device__ int   g_bondfill[BBOND];
__device__ int   g_binned[BBOND * BINCAP];   /* strided bond bins */
__device__ int   g_colpack[NN * CAP];        /* strided row CSR: (eid<<12)|col */

/* ------------------------------ zero counters --------------------------- */
__global__ void k_zero() {
    int i = blockIdx.x * blockDim.x + threadIdx.x;
    if (i < NN) g_rowfill[i] = 0;
    if (i < BBOND) g_bondfill[i] = 0;
}

/* ----------- one-time weight splitting into fragment layout ------------- */
__global__ void __launch_bounds__(128) k_wsplit(const float* __restrict__ W0,
                                                const float* __restrict__ W1) {
    int combo = blockIdx.x;
    int tid = threadIdx.x;
    for (int idx = tid; idx < 2048; idx += 128) {
        int n = idx & 63, kp = idx >> 6;
        float w0 = W1[combo * 4096 + (kp * 2) * 64 + n];
        float w1 = W1[combo * 4096 + (kp * 2 + 1) * 64 + n];
        unsigned hp, lp;
        split2(w0, w1, hp, lp);
        g_W1hi[combo * 2048 + n * 32 + kp] = hp;
        g_W1lo[combo * 2048 + n * 32 + kp] = lp;
    }
    for (int idx = tid; idx < 4096; idx += 128) {
        int n = idx & 63, kp = (idx >> 6) & 31, ph = idx >> 11;
        const float* Wb = W0 + combo * 8192 + ph * 4096;
        float w0 = Wb[(kp * 2) * 64 + n];
        float w1 = Wb[(kp * 2 + 1) * 64 + n];
        unsigned hp, lp;
        split2(w0, w1, hp, lp);
        g_W0hi[combo * 4096 + ph * 2048 + n * 32 + kp] = hp;
        g_W0lo[combo * 4096 + ph * 2048 + n * 32 + kp] = lp;
    }
}

/* --------------------- QKV projections (smem weights) ------------------- */
#define QKV_SMEM (4096 * 3 * 4 + 2048 * 4 + 192 * 4)
__global__ void __launch_bounds__(256) k_qkv(
        const float* __restrict__ emb,
        const float* __restrict__ Qw, const float* __restrict__ Qb,
        const float* __restrict__ Kw, const float* __restrict__ Kb,
        const float* __restrict__ Vw, const float* __restrict__ Vb) {
    extern __shared__ float qs[];
    float* sWq = qs;
    float* sWk = qs + 4096;
    float* sWv = qs + 8192;
    float* seb = qs + 12288;          /* 32 x 64 */
    float* sbq = qs + 14336;
    float* sbk = qs + 14400;
    float* sbv = qs + 14464;
    int tid = threadIdx.x;
    int n0 = blockIdx.x * 32;
    for (int i = tid; i < 1024; i += 256) {
        reinterpret_cast<float4*>(sWq)[i] = reinterpret_cast<const float4*>(Qw)[i];
        reinterpret_cast<float4*>(sWk)[i] = reinterpret_cast<const float4*>(Kw)[i];
        reinterpret_cast<float4*>(sWv)[i] = reinterpret_cast<const float4*>(Vw)[i];
    }
    for (int i = tid; i < 512; i += 256)
        reinterpret_cast<float4*>(seb)[i] =
            reinterpret_cast<const float4*>(emb + (size_t)n0 * 64)[i];
    if (tid < 64) { sbq[tid] = Qb[tid]; sbk[tid] = Kb[tid]; sbv[tid] = Vb[tid]; }
    __syncthreads();
    int k = tid & 63, rg = tid >> 6;   /* 4 groups x 8 rows */
    float aq[8], ak[8], av[8];
#pragma unroll
    for (int j = 0; j < 8; j++) { aq[j] = sbq[k]; ak[j] = sbk[k]; av[j] = sbv[k]; }
#pragma unroll 4
    for (int f = 0; f < 64; f++) {
        float wq = sWq[f * 64 + k], wk = sWk[f * 64 + k], wv = sWv[f * 64 + k];
#pragma unroll
        for (int j = 0; j < 8; j++) {
            float e = seb[(rg * 8 + j) * 64 + f];
            aq[j] = fmaf(e, wq, aq[j]);
            ak[j] = fmaf(e, wk, ak[j]);
            av[j] = fmaf(e, wv, av[j]);
        }
    }
#pragma unroll
    for (int j = 0; j < 8; j++) {
        int row = n0 + rg * 8 + j;
        g_V[row * 64 + k] = av[j];
        float pq = __shfl_xor_sync(0xffffffffu, aq[j], 1);
        float pk = __shfl_xor_sync(0xffffffffu, ak[j], 1);
        if (!(k & 1)) {
            unsigned hp, lp;
            split2(aq[j], pq, hp, lp);
            g_Qhi[row * 32 + (k >> 1)] = hp;
            g_Qlo[row * 32 + (k >> 1)] = lp;
            split2(ak[j], pk, hp, lp);
            g_Khi[row * 32 + (k >> 1)] = hp;
            g_Klo[row * 32 + (k >> 1)] = lp;
        }
    }
}

/* ---------- precompute QW0 / KW0: one (tile, combo, phase) per block ----- */
#define PSTRIDE 36
struct PSmem {
    unsigned Ahi[128 * PSTRIDE];
    unsigned Alo[128 * PSTRIDE];
    unsigned Bhi[64 * PSTRIDE];
    unsigned Blo[64 * PSTRIDE];
};
#define PRE_SMEM ((int)sizeof(PSmem))

__global__ void __launch_bounds__(256, 3) k_pre() {
    extern __shared__ char psraw[];
    PSmem& s = *reinterpret_cast<PSmem*>(psraw);
    int tid = threadIdx.x;
    int lane = tid & 31, wid = tid >> 5;
    int qg = lane >> 2, m4 = lane & 3;
    int mg = wid >> 1, ng = wid & 1;
    int rb = mg * 32, cb = ng * 32;
    int n0 = blockIdx.x * 128;
    int combo = blockIdx.y;
    int ph = blockIdx.z;

    const uint4* Ah4 = reinterpret_cast<const uint4*>(ph ? g_Khi : g_Qhi) + (size_t)n0 * 8;
    const uint4* Al4 = reinterpret_cast<const uint4*>(ph ? g_Klo : g_Qlo) + (size_t)n0 * 8;
    float* dstP = ph ? g_KW0 : g_QW0;

    for (int idx = tid; idx < 1024; idx += 256) {
        int r = idx >> 3, c4 = idx & 7;
        *reinterpret_cast<uint4*>(&s.Ahi[r * PSTRIDE + c4 * 4]) = Ah4[idx];
        *reinterpret_cast<uint4*>(&s.Alo[r * PSTRIDE + c4 * 4]) = Al4[idx];
    }
    {
        const uint4* Bh4 = reinterpret_cast<const uint4*>(g_W0hi) +
                           (size_t)combo * 1024 + ph * 512;
        const uint4* Bl4 = reinterpret_cast<const uint4*>(g_W0lo) +
                           (size_t)combo * 1024 + ph * 512;
        for (int idx = tid; idx < 512; idx += 256) {
            int n = idx >> 3, c4 = idx & 7;
            *reinterpret_cast<uint4*>(&s.Bhi[n * PSTRIDE + c4 * 4]) = Bh4[idx];
            *reinterpret_cast<uint4*>(&s.Blo[n * PSTRIDE + c4 * 4]) = Bl4[idx];
        }
    }
    __syncthreads();

    float acc[2][4][4];
#pragma unroll
    for (int mt = 0; mt < 2; mt++)
#pragma unroll
        for (int nt = 0; nt < 4; nt++)
#pragma unroll
            for (int c = 0; c < 4; c++) acc[mt][nt][c] = 0.f;

#pragma unroll
    for (int kt = 0; kt < 4; kt++) {
        int kp0 = kt * 8 + m4;
        unsigned ah[2][4], al[2][4];
#pragma unroll
        for (int mt = 0; mt < 2; mt++) {
            int r = rb + mt * 16 + qg;
            ah[mt][0] = s.Ahi[r * PSTRIDE + kp0];
            ah[mt][1] = s.Ahi[(r + 8) * PSTRIDE + kp0];
            ah[mt][2] = s.Ahi[r * PSTRIDE + kp0 + 4];
            ah[mt][3] = s.Ahi[(r + 8) * PSTRIDE + kp0 + 4];
            al[mt][0] = s.Alo[r * PSTRIDE + kp0];
            al[mt][1] = s.Alo[(r + 8) * PSTRIDE + kp0];
            al[mt][2] = s.Alo[r * PSTRIDE + kp0 + 4];
            al[mt][3] = s.Alo[(r + 8) * PSTRIDE + kp0 + 4];
        }
#pragma unroll
        for (int nt = 0; nt < 4; nt++) {
            int n = cb + nt * 8 + qg;
            unsigned bh0 = s.Bhi[n * PSTRIDE + kp0];
            unsigned bh1 = s.Bhi[n * PSTRIDE + kp0 + 4];
            unsigned bl0 = s.Blo[n * PSTRIDE + kp0];
            unsigned bl1 = s.Blo[n * PSTRIDE + kp0 + 4];
#pragma unroll
            for (int mt = 0; mt < 2; mt++) {
                mma_bf16(acc[mt][nt], ah[mt][0], ah[mt][1], ah[mt][2], ah[mt][3], bh0, bh1);
                mma_bf16(acc[mt][nt], ah[mt][0], ah[mt][1], ah[mt][2], ah[mt][3], bl0, bl1);
                mma_bf16(acc[mt][nt], al[mt][0], al[mt][1], al[mt][2], al[mt][3], bh0, bh1);
            }
        }
    }

    float* dbase = dstP + (size_t)combo * (NN * DD) + (size_t)n0 * 64;
#pragma unroll
    for (int mt = 0; mt < 2; mt++) {
        int r = rb + mt * 16 + qg;
#pragma unroll
        for (int nt = 0; nt < 4; nt++) {
            int col = cb + nt * 8 + m4 * 2;
            *reinterpret_cast<float2*>(dbase + (size_t)r * 64 + col) =
                make_float2(acc[mt][nt][0], acc[mt][nt][1]);
            *reinterpret_cast<float2*>(dbase + (size_t)(r + 8) * 64 + col) =
                make_float2(acc[mt][nt][2], acc[mt][nt][3]);
        }
    }
}

/* ------- scatter into strided bins / strided CSR (no scan needed) ------- */
__global__ void k_scat(const int* __restrict__ src, const int* __restrict__ dst,
                       const int* __restrict__ bond) {
    __shared__ int sb[BBOND];
    __shared__ int sbase[BBOND];
    int tid = threadIdx.x;
    if (tid < BBOND) sb[tid] = 0;
    __syncthreads();
    int e = blockIdx.x * blockDim.x + tid;
    int b = 0, loc = 0;
    if (e < ET) {
        int eb = (e < E2) ? e : e - E2;
        b = bond[eb];
        loc = atomicAdd(&sb[b], 1);
    }
    __syncthreads();
    if (tid < BBOND) sbase[tid] = atomicAdd(&g_bondfill[tid], sb[tid]);
    __syncthreads();
    if (e < ET) {
        g_binned[b * BINCAP + sbase[b] + loc] = e;
        int row, col;
        if (e < E2) { row = src[e]; col = dst[e]; }
        else        { row = dst[e - E2]; col = src[e - E2]; }
        int p2 = atomicAdd(&g_rowfill[row], 1);
        if (p2 < CAP) g_colpack[row * CAP + p2] = (e << 12) | col;
    }
}

/* ----------- edge-MLP score kernel: mma.sync bf16-split (3 terms) ------- */
#define ASTRIDE 36
struct ESmem {
    unsigned Ahi[128 * ASTRIDE];
    unsigned Alo[128 * ASTRIDE];
    unsigned Bhi[64 * ASTRIDE];
    unsigned Blo[64 * ASTRIDE];
    float red[2][128];
    float b0v[64], b1v[64], W2v[64];
    int eid[128], sn[128], dn[128];
};
#define EDGE_SMEM ((int)sizeof(ESmem))

__global__ void __launch_bounds__(256, 3)
k_edges(const int* __restrict__ src, const int* __restrict__ dst,
        const float* __restrict__ b0,
        const float* __restrict__ b1, const float* __restrict__ W2,
        const float* __restrict__ b2) {
    extern __shared__ char smraw[];
    ESmem& s = *reinterpret_cast<ESmem*>(smraw);
    int tid = threadIdx.x;
    int lane = tid & 31, wid = tid >> 5;

    /* tile mapping from per-bond counts (strided bins) */
    int t = blockIdx.x;
    int bt = -1, base = 0, nE = 0;
#pragma unroll
    for (int b = 0; b < BBOND; b++) {
        int cnt = g_bondfill[b];
        int nt = (cnt + 127) >> 7;
        if (bt < 0) {
            if (t < nt) { bt = b; base = b * BINCAP + t * 128; nE = min(128, cnt - t * 128); }
            else t -= nt;
        }
    }
    if (bt < 0) return;
    int h = blockIdx.y;
    int combo = bt * 4 + h;

    if (tid < 64) {
        s.b0v[tid] = b0[combo * 64 + tid];
        s.b1v[tid] = b1[combo * 64 + tid];
        s.W2v[tid] = W2[combo * 64 + tid];
    }
    if (tid < nE) {
        int e = g_binned[base + tid];
        s.eid[tid] = e;
        if (e < E2) { s.sn[tid] = src[e];      s.dn[tid] = dst[e]; }
        else        { s.sn[tid] = dst[e - E2]; s.dn[tid] = src[e - E2]; }
    }
    /* stage B: pure copy of pre-split W1 */
    {
        const uint4* Bh4 = reinterpret_cast<const uint4*>(g_W1hi) + (size_t)combo * 512;
        const uint4* Bl4 = reinterpret_cast<const uint4*>(g_W1lo) + (size_t)combo * 512;
        for (int idx = tid; idx < 512; idx += 256) {
            int n = idx >> 3, c4 = idx & 7;
            *reinterpret_cast<uint4*>(&s.Bhi[n * ASTRIDE + c4 * 4]) = Bh4[idx];
            *reinterpret_cast<uint4*>(&s.Blo[n * ASTRIDE + c4 * 4]) = Bl4[idx];
        }
    }
    __syncthreads();

    /* stage A = relu(QW0[s] + KW0[d] + b0), coalesced: 16 threads per row */
    {
        int g = tid >> 4, v = tid & 15;
        float4 bb = *reinterpret_cast<const float4*>(&s.b0v[v * 4]);
        const float4* QW4 = reinterpret_cast<const float4*>(g_QW0) + (size_t)combo * NN * 16;
        const float4* KW4 = reinterpret_cast<const float4*>(g_KW0) + (size_t)combo * NN * 16;
#pragma unroll
        for (int i = 0; i < 8; i++) {
            int r = i * 16 + g;
            unsigned h0 = 0, l0 = 0, h1 = 0, l1 = 0;
            if (r < nE) {
                int sN = s.sn[r], dN = s.dn[r];
                float4 q = QW4[(size_t)sN * 16 + v];
                float4 kk = KW4[(size_t)dN * 16 + v];
                float e0 = fmaxf(q.x + kk.x + bb.x, 0.f);
                float e1 = fmaxf(q.y + kk.y + bb.y, 0.f);
                float e2 = fmaxf(q.z + kk.z + bb.z, 0.f);
                float e3 = fmaxf(q.w + kk.w + bb.w, 0.f);
                split2(e0, e1, h0, l0);
                split2(e2, e3, h1, l1);
            }
            s.Ahi[r * ASTRIDE + v * 2]     = h0;
            s.Alo[r * ASTRIDE + v * 2]     = l0;
            s.Ahi[r * ASTRIDE + v * 2 + 1] = h1;
            s.Alo[r * ASTRIDE + v * 2 + 1] = l1;
        }
    }
    __syncthreads();

    /* MMA mainloop: mt=2 x nt=4 per warp, fragments loaded once per kt */
    int qg = lane >> 2, m4 = lane & 3;
    int mg = wid >> 1, ng = wid & 1;
    int rb = mg * 32, cb = ng * 32;
    float acc[2][4][4];
#pragma unroll
    for (int mt = 0; mt < 2; mt++)
#pragma unroll
        for (int nt = 0; nt < 4; nt++)
#pragma unroll
            for (int c = 0; c < 4; c++) acc[mt][nt][c] = 0.f;

#pragma unroll
    for (int kt = 0; kt < 4; kt++) {
        int kp0 = kt * 8 + m4;
        unsigned ah[2][4], al[2][4];
#pragma unroll
        for (int mt = 0; mt < 2; mt++) {
            int r = rb + mt * 16 + qg;
            ah[mt][0] = s.Ahi[r * ASTRIDE + kp0];
            ah[mt][1] = s.Ahi[(r + 8) * ASTRIDE + kp0];
            ah[mt][2] = s.Ahi[r * ASTRIDE + kp0 + 4];
            ah[mt][3] = s.Ahi[(r + 8) * ASTRIDE + kp0 + 4];
            al[mt][0] = s.Alo[r * ASTRIDE + kp0];
            al[mt][1] = s.Alo[(r + 8) * ASTRIDE + kp0];
            al[mt][2] = s.Alo[r * ASTRIDE + kp0 + 4];
            al[mt][3] = s.Alo[(r + 8) * ASTRIDE + kp0 + 4];
        }
#pragma unroll
        for (int nt = 0; nt < 4; nt++) {
            int n = cb + nt * 8 + qg;
            unsigned bh0 = s.Bhi[n * ASTRIDE + kp0];
            unsigned bh1 = s.Bhi[n * ASTRIDE + kp0 + 4];
            unsigned bl0 = s.Blo[n * ASTRIDE + kp0];
            unsigned bl1 = s.Blo[n * ASTRIDE + kp0 + 4];
#pragma unroll
            for (int mt = 0; mt < 2; mt++) {
                mma_bf16(acc[mt][nt], ah[mt][0], ah[mt][1], ah[mt][2], ah[mt][3], bh0, bh1);
                mma_bf16(acc[mt][nt], ah[mt][0], ah[mt][1], ah[mt][2], ah[mt][3], bl0, bl1);
                mma_bf16(acc[mt][nt], al[mt][0], al[mt][1], al[mt][2], al[mt][3], bh0, bh1);
            }
        }
    }

    /* epilogue: relu + W2 partial dot over this warp's 32 cols */
    float p[4] = {0.f, 0.f, 0.f, 0.f};
#pragma unroll
    for (int nt = 0; nt < 4; nt++) {
#pragma unroll
        for (int j = 0; j < 2; j++) {
            int col = cb + nt * 8 + m4 * 2 + j;
            float bb = s.b1v[col], ww = s.W2v[col];
            p[0] = fmaf(fmaxf(acc[0][nt][j] + bb, 0.f), ww, p[0]);
            p[1] = fmaf(fmaxf(acc[0][nt][2 + j] + bb, 0.f), ww, p[1]);
            p[2] = fmaf(fmaxf(acc[1][nt][j] + bb, 0.f), ww, p[2]);
            p[3] = fmaf(fmaxf(acc[1][nt][2 + j] + bb, 0.f), ww, p[3]);
        }
    }
#pragma unroll
    for (int i = 0; i < 4; i++) {
        p[i] += __shfl_xor_sync(0xffffffffu, p[i], 1);
        p[i] += __shfl_xor_sync(0xffffffffu, p[i], 2);
    }
    if (m4 == 0) {
        s.red[ng][rb + qg]      = p[0];
        s.red[ng][rb + qg + 8]  = p[1];
        s.red[ng][rb + qg + 16] = p[2];
        s.red[ng][rb + qg + 24] = p[3];
    }
    __syncthreads();
    if (tid < 128 && tid < nE) {
        float sc = s.red[0][tid] + s.red[1][tid] + b2[combo];
        sc = (sc >= 0.f) ? sc : 0.2f * sc;
        g_scores[h * ET + s.eid[tid]] = sc;
    }
}

/* -------------- per-row sparse softmax (dedup, last-write-wins) --------- */
struct SoftSmem {
    float VS[CAP * 64];
    float scs[4][CAP];
    int   pk[CAP];
    int   srt[CAP];
    unsigned char kept[CAP];
};

__global__ void __launch_bounds__(128) k_soft() {
    extern __shared__ char smem_raw[];
    SoftSmem& s = *reinterpret_cast<SoftSmem*>(smem_raw);
    int row = blockIdx.x;
    int tid = threadIdx.x;
    int deg = g_rowfill[row];
    if (deg > CAP) deg = CAP;
    for (int a = tid; a < deg; a += 128) s.pk[a] = g_colpack[row * CAP + a];
    __syncthreads();
    for (int a = tid; a < deg; a += 128) {
        int p = s.pk[a];
        int rk = 0;
        for (int b = 0; b < deg; b++) rk += (s.pk[b] < p);
        s.srt[rk] = p;
    }
    __syncthreads();
    for (int a = tid; a < deg; a += 128) {
        int col = s.srt[a] & 0xFFF;
        unsigned char kf = 1;
        for (int b = a + 1; b < deg; b++)
            if ((s.srt[b] & 0xFFF) == col) { kf = 0; break; }
        s.kept[a] = kf;
    }
    __syncthreads();
    for (int h2 = 0; h2 < 4; h2++)
        for (int a = tid; a < deg; a += 128)
            s.scs[h2][a] = g_scores[h2 * ET + (s.srt[a] >> 12)];
    for (int idx = tid; idx < deg * 16; idx += 128) {
        int a = idx >> 4, cv = idx & 15;
        int col = s.srt[a] & 0xFFF;
        reinterpret_cast<float4*>(s.VS + a * 64)[cv] =
            reinterpret_cast<const float4*>(g_V + col * 64)[cv];
    }
    __syncthreads();

    int lane = tid & 31, h = tid >> 5;
    float m = -1e30f;
    for (int a = lane; a < deg; a += 32)
        if (s.kept[a]) m = fmaxf(m, s.scs[h][a]);
#pragma unroll
    for (int o = 16; o > 0; o >>= 1) m = fmaxf(m, __shfl_xor_sync(0xffffffffu, m, o));
    float dsum = 0.f;
    for (int a = lane; a < deg; a += 32) {
        float p = s.kept[a] ? __expf(s.scs[h][a] - m) : 0.f;
        s.scs[h][a] = p;
        dsum += p;
    }
#pragma unroll
    for (int o = 16; o > 0; o >>= 1) dsum += __shfl_xor_sync(0xffffffffu, dsum, o);
    __syncwarp();
    float inv = 1.f / dsum;
    float acc0 = 0.f, acc1 = 0.f, acc2 = 0.f, acc3 = 0.f;
    int a = 0;
    for (; a + 1 < deg; a += 2) {
        float w0 = s.scs[h][a] * inv;
        float w1 = s.scs[h][a + 1] * inv;
        acc0 = fmaf(w0, s.VS[a * 64 + lane], acc0);
        acc1 = fmaf(w0, s.VS[a * 64 + 32 + lane], acc1);
        acc2 = fmaf(w1, s.VS[(a + 1) * 64 + lane], acc2);
        acc3 = fmaf(w1, s.VS[(a + 1) * 64 + 32 + lane], acc3);
    }
    if (a < deg) {
        float w0 = s.scs[h][a] * inv;
        acc0 = fmaf(w0, s.VS[a * 64 + lane], acc0);
        acc1 = fmaf(w0, s.VS[a * 64 + 32 + lane], acc1);
    }
    g_att[row * 256 + h * 64 + lane]      = acc0 + acc2;
    g_att[row * 256 + h * 64 + 32 + lane] = acc1 + acc3;
}

/* ------------------------------ final projection ------------------------ */
__global__ void __launch_bounds__(256) k_proj(const float* __restrict__ Pw,
                                              const float* __restrict__ Pb,
                                              float* __restrict__ out) {
    __shared__ float ats[16 * 256];
    int tid = threadIdx.x;
    int r0 = blockIdx.x * 16;
    for (int idx = tid; idx < 1024; idx += 256)
        reinterpret_cast<float4*>(ats)[idx] =
            reinterpret_cast<const float4*>(g_att + (size_t)r0 * 256)[idx];
    __syncthreads();
    int c = tid & 63, rg = tid >> 6;
    float acc[4];
    float pb = Pb[c];
#pragma unroll
    for (int r = 0; r < 4; r++) acc[r] = pb;
#pragma unroll 4
    for (int k = 0; k < 256; k++) {
        float w = Pw[k * 64 + c];
#pragma unroll
        for (int r = 0; r < 4; r++)
            acc[r] = fmaf(ats[(rg * 4 + r) * 256 + k], w, acc[r]);
    }
#pragma unroll
    for (int r = 0; r < 4; r++)
        out[(r0 + rg * 4 + r) * 64 + c] = acc[r];
}

/* ------------------------------ launcher -------------------------------- */
extern "C" void kernel_launch(void* const* d_in, const int* in_sizes, int n_in,
                              void* d_out, int out_size) {
    const float* emb = (const float*)d_in[0];
    const float* Qw  = (const float*)d_in[1];
    const float* Qb  = (const float*)d_in[2];
    const float* Kw  = (const float*)d_in[3];
    const float* Kb  = (const float*)d_in[4];
    const float* Vw  = (const float*)d_in[5];
    const float* Vb  = (const float*)d_in[6];
    const float* W0  = (const float*)d_in[7];
    const float* b0  = (const float*)d_in[8];
    const float* W1  = (const float*)d_in[9];
    const float* b1  = (const float*)d_in[10];
    const float* W2  = (const float*)d_in[11];
    const float* b2  = (const float*)d_in[12];
    const float* Pw  = (const float*)d_in[13];
    const float* Pb  = (const float*)d_in[14];
    const int*   src = (const int*)d_in[15];
    const int*   dst = (const int*)d_in[16];
    const int*   bnd = (const int*)d_in[17];
    float* out = (float*)d_out;

    cudaFuncSetAttribute(k_qkv, cudaFuncAttributeMaxDynamicSharedMemorySize, QKV_SMEM);
    cudaFuncSetAttribute(k_pre, cudaFuncAttributeMaxDynamicSharedMemorySize, PRE_SMEM);
    cudaFuncSetAttribute(k_edges, cudaFuncAttributeMaxDynamicSharedMemorySize, EDGE_SMEM);
    cudaFuncSetAttribute(k_soft, cudaFuncAttributeMaxDynamicSharedMemorySize,
                         (int)sizeof(SoftSmem));

    k_zero<<<16, 256>>>();
    k_wsplit<<<16, 128>>>(W0, W1);
    k_qkv<<<NN / 32, 256, QKV_SMEM>>>(emb, Qw, Qb, Kw, Kb, Vw, Vb);
    k_scat<<<ET / 256, 256>>>(src, dst, bnd);
    k_pre<<<dim3(NN / 128, 16, 2), 256, PRE_SMEM>>>();
    k_edges<<<dim3(579, 4), 256, EDGE_SMEM>>>(src, dst, b0, b1, W2, b2);
    k_soft<<<NN, 128, sizeof(SoftSmem)>>>();
    k_proj<<<NN / 16, 256>>>(Pw, Pb, out);
}